// round 8
// baseline (speedup 1.0000x reference)
#include <cuda_runtime.h>
#include <cuda_fp16.h>
#include <math.h>

#define N_NODES 50000
#define EMB 35
#define DEG 32

// g_embu: packed emb rows, 32 uints (128B) per node, 128B-aligned.
//   uints 0..17 : half2 pairs, cols (2k, 2k+1); col 35 = 0
//   uint  18    : s_dst as fp32 bits
//   uint  19    : 0   (uints 20..31 never read)
__device__ __align__(128) unsigned g_embu[4][N_NODES * 32];
__device__ float g_ssrc[4][N_NODES];
__device__ float g_m[4][N_NODES * 40];     // fp32 messages; cols >=35 garbage

struct Params {
    const float* fa; const float* fb;
    const int*   dst[4];
    const float* W[4]; const float* bv[4]; const float* att[4];
    const float* W1; const float* b1; const float* alpha; const float* W2; const float* b2;
    float* out;
};

// ---- packed f32x2 helpers (sm_103a FFMA2) ----------------------------------
__device__ __forceinline__ unsigned long long pack2(float lo, float hi) {
    unsigned long long r;
    asm("mov.b64 %0, {%1,%2};" : "=l"(r) : "f"(lo), "f"(hi));
    return r;
}
__device__ __forceinline__ void unpack2(unsigned long long v, float& lo, float& hi) {
    asm("mov.b64 {%0,%1}, %2;" : "=f"(lo), "=f"(hi) : "l"(v));
}
__device__ __forceinline__ void fma2(unsigned long long& d, unsigned long long a, unsigned long long b) {
    asm("fma.rn.f32x2 %0, %1, %2, %0;" : "+l"(d) : "l"(a), "l"(b));
}
__device__ __forceinline__ void lds_v2u64(const float* sp, unsigned long long& a, unsigned long long& b) {
    unsigned int addr = (unsigned int)__cvta_generic_to_shared(sp);
    asm("ld.shared.v2.u64 {%0,%1}, [%2];" : "=l"(a), "=l"(b) : "r"(addr));
}

// ---------------------------------------------------------------------------
// Kernel 1: transform + scores. Block = 256 rows, 128 threads (2 rows/thread)
// so each shared weight LDS.128 feeds 8 FFMA2. Packed uint output rows.
// ---------------------------------------------------------------------------
#define TK_ROWS 256
__global__ void __launch_bounds__(128) transform_kernel(Params p) {
    const int agg = blockIdx.y;
    __shared__ __align__(16) float Ws[35 * 36];   // padded cols, col35 = 0
    __shared__ __align__(16) float tile[TK_ROWS * 41];
    __shared__ float bs[36], a1s[35], a2s[36];

    {
        const float* W = p.W[agg];
        for (int t = threadIdx.x; t < 35 * 36; t += 128) {
            int i = t / 36, c = t - 36 * i;
            Ws[t] = (c < 35) ? W[i * 35 + c] : 0.0f;
        }
        const float* bb = p.bv[agg];
        for (int t = threadIdx.x; t < 36; t += 128) bs[t] = (t < 35) ? bb[t] : 0.0f;
        const float* at = p.att[agg];
        for (int t = threadIdx.x; t < 36; t += 128) {
            if (t < 35) a1s[t] = at[t];
            a2s[t] = (t < 35) ? at[35 + t] : 0.0f;
        }
    }

    const int base = blockIdx.x * TK_ROWS;
    const int cnt  = min(TK_ROWS, N_NODES - base);
    const int tid  = threadIdx.x;
    const float* ftab = (agg < 2) ? p.fb : p.fa;
    const float* fsc  = (agg < 2) ? p.fa : p.fb;

    // ---- phase A: s_src ----
    __syncthreads();
    {
        int idx = tid, r = tid / 35, c = tid - 35 * (tid / 35);
        for (; idx < cnt * 35; idx += 128) {
            tile[r * 41 + c] = fsc[base * 35 + idx];
            r += 3; c += 23; if (c >= 35) { c -= 35; r += 1; }
        }
    }
    __syncthreads();
    for (int rr = tid; rr < cnt; rr += 128) {
        float s1 = 0.0f;
        const float* xr = tile + rr * 41;
#pragma unroll
        for (int i = 0; i < 35; i++) s1 += xr[i] * a1s[i];
        g_ssrc[agg][base + rr] = s1;
    }
    __syncthreads();

    // ---- phase B: new_emb = ftab @ W + b for rows tid, tid+128 ----
    {
        int idx = tid, r = tid / 35, c = tid - 35 * (tid / 35);
        for (; idx < cnt * 35; idx += 128) {
            tile[r * 41 + c] = ftab[base * 35 + idx];
            r += 3; c += 23; if (c >= 35) { c -= 35; r += 1; }
        }
    }
    __syncthreads();
    {
        unsigned long long oA[18], oB[18];
#pragma unroll
        for (int k = 0; k < 18; k++) {
            unsigned long long bv = pack2(bs[2 * k], bs[2 * k + 1]);
            oA[k] = bv; oB[k] = bv;
        }
        const float* x0 = tile + tid * 41;
        const float* x1 = tile + (tid + 128) * 41;
#pragma unroll
        for (int i = 0; i < 35; i++) {
            float f0 = x0[i], f1 = x1[i];
            unsigned long long ff0 = pack2(f0, f0);
            unsigned long long ff1 = pack2(f1, f1);
            const float* wr = Ws + i * 36;
#pragma unroll
            for (int k = 0; k < 9; k++) {
                unsigned long long wa, wb;
                lds_v2u64(wr + 4 * k, wa, wb);
                fma2(oA[2 * k],     ff0, wa);
                fma2(oA[2 * k + 1], ff0, wb);
                fma2(oB[2 * k],     ff1, wa);
                fma2(oB[2 * k + 1], ff1, wb);
            }
        }
        // pack own rows into tile as uints (no cross-thread hazard: own rows only)
        unsigned* tu0 = (unsigned*)tile + tid * 41;
        unsigned* tu1 = (unsigned*)tile + (tid + 128) * 41;
        float sdA = 0.0f, sdB = 0.0f;
#pragma unroll
        for (int k = 0; k < 18; k++) {
            float lo, hi;
            unpack2(oA[k], lo, hi);
            sdA = fmaf(lo, a2s[2 * k], fmaf(hi, a2s[2 * k + 1], sdA));
            __half2 h = __floats2half2_rn(lo, hi);
            tu0[k] = *reinterpret_cast<unsigned*>(&h);
            unpack2(oB[k], lo, hi);
            sdB = fmaf(lo, a2s[2 * k], fmaf(hi, a2s[2 * k + 1], sdB));
            h = __floats2half2_rn(lo, hi);
            tu1[k] = *reinterpret_cast<unsigned*>(&h);
        }
        tu0[18] = __float_as_uint(sdA); tu0[19] = 0u;
        tu1[18] = __float_as_uint(sdB); tu1[19] = 0u;
    }
    __syncthreads();

    // ---- coalesced store: 20 uints per row ----
    {
        const unsigned* tu = (const unsigned*)tile;
        unsigned* om = g_embu[agg];
        int idx = tid, r = tid / 20, c = tid - 20 * (tid / 20);
        for (; idx < cnt * 20; idx += 128) {
            om[(size_t)(base + r) * 32 + c] = tu[r * 41 + c];
            r += 6; c += 8; if (c >= 20) { c -= 20; r += 1; }
        }
    }
}

// ---------------------------------------------------------------------------
// Kernel 2: aggregation. One warp per (agg,node). One edge per gather
// instruction: 32 lanes read 4B (half2) of the SAME 128B row -> 1 line/LDG.
// Lane q accumulates cols (2q,2q+1); no reduction shuffles needed.
// ---------------------------------------------------------------------------
__global__ void __launch_bounds__(256) aggregate_kernel(Params p) {
    __shared__ uint2 sh[8][32];          // {byte offset of row, w bits}
    const int wb   = threadIdx.x >> 5;
    const int lane = threadIdx.x & 31;
    const int gw   = blockIdx.x * 8 + wb;
    const int agg  = gw / N_NODES;
    const int node = gw - agg * N_NODES;

    const unsigned* tab = g_embu[agg];
    int d = p.dst[agg][node * DEG + lane];
    unsigned off = (unsigned)d * 128u;                  // byte offset of row
    float sdst = __uint_as_float(tab[(off >> 2) + 18]); // embedded s_dst
    float z = g_ssrc[agg][node] + sdst;

    float u  = __expf(z);
    float el = (z > 0.0f) ? z : 0.1f * (u - 1.0f);      // elu(alpha=0.1)
    float w  = __expf(el);

    float den = w;
#pragma unroll
    for (int o = 16; o; o >>= 1) den += __shfl_xor_sync(0xffffffffu, den, o);

    sh[wb][lane] = make_uint2(off, __float_as_uint(w));
    __syncwarp();

    const bool act = lane < 18;
    float ax = 0.0f, ay = 0.0f;
#pragma unroll
    for (int t = 0; t < 32; t++) {
        uint2 ew = sh[wb][t];
        if (act) {
            unsigned v = tab[(ew.x >> 2) + lane];       // half2 of cols 2q,2q+1
            float2 f = __half22float2(*reinterpret_cast<__half2*>(&v));
            float wt = __uint_as_float(ew.y);
            ax += wt * f.x; ay += wt * f.y;
        }
    }
    if (act) {
        float inv = 1.0f / den;
        *(float2*)(g_m[agg] + (size_t)node * 40 + 2 * lane) = make_float2(ax * inv, ay * inv);
    }
}

// ---------------------------------------------------------------------------
// Kernel 3: update MLP 105->70(PReLU)->35 (unchanged structure).
// ---------------------------------------------------------------------------
#define UPD_W1T   0
#define UPD_W2    (70 * 108)
#define UPD_B1    (UPD_W2 + 70 * 36)
#define UPD_B2    (UPD_B1 + 72)
#define UPD_TILE  (UPD_B2 + 40)
#define UPD_FLOATS (UPD_TILE + 128 * 37)
#define UPD_SMEM_BYTES (UPD_FLOATS * 4)

__global__ void __launch_bounds__(128) update_kernel(Params p) {
    extern __shared__ __align__(16) float usm[];
    float* W1T  = usm + UPD_W1T;
    float* W2s  = usm + UPD_W2;
    float* b1s  = usm + UPD_B1;
    float* b2s  = usm + UPD_B2;
    float* tile = usm + UPD_TILE;
    const int tid = threadIdx.x;

    for (int t = tid; t < 70 * 108; t += 128) {
        int j = t / 108, s = t - 108 * j;
        int os = (s < 35) ? s : (s == 35) ? -1 : (s < 71) ? s - 1 : (s == 71) ? -1 : (s < 107) ? s - 2 : -1;
        W1T[t] = (os >= 0) ? p.W1[os * 70 + j] : 0.0f;
    }
    for (int t = tid; t < 70 * 36; t += 128) {
        int j = t / 36, c = t - 36 * j;
        W2s[t] = (c < 35) ? p.W2[j * 35 + c] : 0.0f;
    }
    for (int t = tid; t < 70; t += 128) b1s[t] = p.b1[t];
    for (int t = tid; t < 36; t += 128) b2s[t] = (t < 35) ? p.b2[t] : 0.0f;
    float alpha_v = p.alpha[0];

    const int NBLK = (N_NODES + 127) / 128;
    const bool sideA = (blockIdx.x < NBLK);
    const int  bx   = sideA ? blockIdx.x : blockIdx.x - NBLK;
    const int  base = bx * 128;
    const int  cnt  = min(128, N_NODES - base);
    const float* fsrc = sideA ? p.fa : p.fb;
    const float* mpg  = (sideA ? g_m[0] : g_m[2]);
    const float* mng  = (sideA ? g_m[1] : g_m[3]);

    unsigned long long xp[54];

    __syncthreads();
    {
        int idx = tid, r = tid / 35, c = tid - 35 * (tid / 35);
        for (; idx < cnt * 35; idx += 128) {
            tile[r * 37 + c] = fsrc[base * 35 + idx];
            r += 3; c += 23; if (c >= 35) { c -= 35; r += 1; }
        }
    }
    __syncthreads();
    if (tid < cnt) {
        const float* xr = tile + tid * 37;
#pragma unroll
        for (int k = 0; k < 17; k++) xp[k] = pack2(xr[2 * k], xr[2 * k + 1]);
        xp[17] = pack2(xr[34], 0.0f);
    }
    __syncthreads();
    {
        int idx = tid, r = tid / 35, c = tid - 35 * (tid / 35);
        for (; idx < cnt * 35; idx += 128) {
            tile[r * 37 + c] = mpg[(size_t)(base + r) * 40 + c];
            r += 3; c += 23; if (c >= 35) { c -= 35; r += 1; }
        }
    }
    __syncthreads();
    if (tid < cnt) {
        const float* xr = tile + tid * 37;
#pragma unroll
        for (int k = 0; k < 17; k++) xp[18 + k] = pack2(xr[2 * k], xr[2 * k + 1]);
        xp[35] = pack2(xr[34], 0.0f);
    }
    __syncthreads();
    {
        int idx = tid, r = tid / 35, c = tid - 35 * (tid / 35);
        for (; idx < cnt * 35; idx += 128) {
            tile[r * 37 + c] = mng[(size_t)(base + r) * 40 + c];
            r += 3; c += 23; if (c >= 35) { c -= 35; r += 1; }
        }
    }
    __syncthreads();
    if (tid < cnt) {
        const float* xr = tile + tid * 37;
#pragma unroll
        for (int k = 0; k < 17; k++) xp[36 + k] = pack2(xr[2 * k], xr[2 * k + 1]);
        xp[53] = pack2(xr[34], 0.0f);
    }

    if (tid < cnt) {
        unsigned long long o2[18];
#pragma unroll
        for (int k = 0; k < 18; k++) o2[k] = pack2(b2s[2 * k], b2s[2 * k + 1]);

        for (int j = 0; j < 70; j++) {
            unsigned long long h2a = 0ull, h2b = 0ull;
            const float* wr = W1T + j * 108;
#pragma unroll
            for (int qq = 0; qq < 27; qq++) {
                unsigned long long wa, wb;
                lds_v2u64(wr + 4 * qq, wa, wb);
                fma2(h2a, xp[2 * qq], wa);
                fma2(h2b, xp[2 * qq + 1], wb);
            }
            float a0, a1, b0, b1v;
            unpack2(h2a, a0, a1); unpack2(h2b, b0, b1v);
            float hj = b1s[j] + ((a0 + a1) + (b0 + b1v));
            hj = (hj > 0.0f) ? hj : alpha_v * hj;
            unsigned long long hh = pack2(hj, hj);
            const float* w2r = W2s + j * 36;
#pragma unroll
            for (int k = 0; k < 9; k++) {
                unsigned long long wa, wb;
                lds_v2u64(w2r + 4 * k, wa, wb);
                fma2(o2[2 * k], hh, wa);
                fma2(o2[2 * k + 1], hh, wb);
            }
        }
        float* tr = tile + tid * 37;
#pragma unroll
        for (int k = 0; k < 18; k++) {
            float lo, hi; unpack2(o2[k], lo, hi);
            if (2 * k     < 35) tr[2 * k]     = lo;
            if (2 * k + 1 < 35) tr[2 * k + 1] = hi;
        }
    }
    __syncthreads();

    const int gbase = (sideA ? 0 : N_NODES) + base;
    {
        int idx = tid, r = tid / 35, c = tid - 35 * (tid / 35);
        for (; idx < cnt * 35; idx += 128) {
            p.out[gbase * 35 + idx] = tile[r * 37 + c];
            r += 3; c += 23; if (c >= 35) { c -= 35; r += 1; }
        }
    }
}

// ---------------------------------------------------------------------------
extern "C" void kernel_launch(void* const* d_in, const int* in_sizes, int n_in,
                              void* d_out, int out_size) {
    Params p;
    p.fa = (const float*)d_in[0];
    p.fb = (const float*)d_in[1];
    p.dst[0] = (const int*)d_in[2];
    p.dst[1] = (const int*)d_in[3];
    p.dst[2] = (const int*)d_in[4];
    p.dst[3] = (const int*)d_in[5];
    for (int k = 0; k < 4; k++) {
        p.W[k]   = (const float*)d_in[6 + 3 * k];
        p.bv[k]  = (const float*)d_in[7 + 3 * k];
        p.att[k] = (const float*)d_in[8 + 3 * k];
    }
    p.W1    = (const float*)d_in[18];
    p.b1    = (const float*)d_in[19];
    p.alpha = (const float*)d_in[20];
    p.W2    = (const float*)d_in[21];
    p.b2    = (const float*)d_in[22];
    p.out   = (float*)d_out;

    dim3 g1((N_NODES + TK_ROWS - 1) / TK_ROWS, 4);
    transform_kernel<<<g1, 128>>>(p);

    aggregate_kernel<<<(4 * N_NODES) / 8, 256>>>(p);

    cudaFuncSetAttribute(update_kernel, cudaFuncAttributeMaxDynamicSharedMemorySize, UPD_SMEM_BYTES);
    update_kernel<<<2 * ((N_NODES + 127) / 128), 128, UPD_SMEM_BYTES>>>(p);
}

// round 12
// speedup vs baseline: 1.8621x; 1.8621x over previous
#include <cuda_runtime.h>
#include <cuda_fp16.h>
#include <math.h>

#define N_NODES 50000
#define EMB 35
#define DEG 32

// g_emb: fp16 transformed tables, 64-half rows (128B, line-aligned).
// halves 0..34 = new_emb, 35..39 = 0, 40..63 never read.
__device__ __align__(128) __half g_emb[4][N_NODES * 64];
__device__ float g_sdst[4][N_NODES];     // compact: good L1 locality for gather
__device__ float g_ssrc[4][N_NODES];
__device__ float g_m[4][N_NODES * 40];   // fp32 messages; cols >=35 garbage

struct Params {
    const float* fa; const float* fb;
    const int*   dst[4];
    const float* W[4]; const float* bv[4]; const float* att[4];
    const float* W1; const float* b1; const float* alpha; const float* W2; const float* b2;
    float* out;
};

// ---- packed f32x2 helpers (sm_103a FFMA2) ----------------------------------
__device__ __forceinline__ unsigned long long pack2(float lo, float hi) {
    unsigned long long r;
    asm("mov.b64 %0, {%1,%2};" : "=l"(r) : "f"(lo), "f"(hi));
    return r;
}
__device__ __forceinline__ void unpack2(unsigned long long v, float& lo, float& hi) {
    asm("mov.b64 {%0,%1}, %2;" : "=f"(lo), "=f"(hi) : "l"(v));
}
__device__ __forceinline__ void fma2(unsigned long long& d, unsigned long long a, unsigned long long b) {
    asm("fma.rn.f32x2 %0, %1, %2, %0;" : "+l"(d) : "l"(a), "l"(b));
}
__device__ __forceinline__ void lds_v2u64(const float* sp, unsigned long long& a, unsigned long long& b) {
    unsigned int addr = (unsigned int)__cvta_generic_to_shared(sp);
    asm("ld.shared.v2.u64 {%0,%1}, [%2];" : "=l"(a), "=l"(b) : "r"(addr));
}

// ---------------------------------------------------------------------------
// Kernel 1: per-agg transform + attention scores. Block = 128 rows
// (R5 structure: one row/thread, regs ~68, occ ~37%).
// ---------------------------------------------------------------------------
__global__ void __launch_bounds__(128) transform_kernel(Params p) {
    const int agg = blockIdx.y;
    __shared__ __align__(16) float Ws[35 * 36];     // padded cols, col35 = 0
    __shared__ float tile[128 * 41];
    __shared__ float bs[36], a1s[35], a2s[35];

    {
        const float* W = p.W[agg];
        for (int t = threadIdx.x; t < 35 * 36; t += 128) {
            int i = t / 36, c = t - 36 * i;
            Ws[t] = (c < 35) ? W[i * 35 + c] : 0.0f;
        }
        const float* bb = p.bv[agg];
        for (int t = threadIdx.x; t < 36; t += 128) bs[t] = (t < 35) ? bb[t] : 0.0f;
        const float* at = p.att[agg];
        for (int t = threadIdx.x; t < 35; t += 128) { a1s[t] = at[t]; a2s[t] = at[35 + t]; }
    }

    const int base = blockIdx.x * 128;
    const int cnt  = min(128, N_NODES - base);
    const int tid  = threadIdx.x;
    const float* ftab = (agg < 2) ? p.fb : p.fa;
    const float* fsc  = (agg < 2) ? p.fa : p.fb;

    // ---- phase A: s_src ----
    __syncthreads();
    {
        int idx = tid, r = tid / 35, c = tid - 35 * (tid / 35);
        for (; idx < cnt * 35; idx += 128) {
            tile[r * 41 + c] = fsc[base * 35 + idx];
            r += 3; c += 23; if (c >= 35) { c -= 35; r += 1; }
        }
    }
    __syncthreads();
    if (tid < cnt) {
        float s1 = 0.0f;
        const float* xr = tile + tid * 41;
#pragma unroll
        for (int i = 0; i < 35; i++) s1 += xr[i] * a1s[i];
        g_ssrc[agg][base + tid] = s1;
    }
    __syncthreads();

    // ---- phase B: new_emb = ftab @ W + b, s_dst ----
    {
        int idx = tid, r = tid / 35, c = tid - 35 * (tid / 35);
        for (; idx < cnt * 35; idx += 128) {
            tile[r * 41 + c] = ftab[base * 35 + idx];
            r += 3; c += 23; if (c >= 35) { c -= 35; r += 1; }
        }
    }
    __syncthreads();
    if (tid < cnt) {
        unsigned long long o2[18];
#pragma unroll
        for (int k = 0; k < 18; k++) o2[k] = pack2(bs[2 * k], bs[2 * k + 1]);
        const float* xr = tile + tid * 41;
#pragma unroll
        for (int i = 0; i < 35; i++) {
            float fi = xr[i];
            unsigned long long ff = pack2(fi, fi);
            const float* wr = Ws + i * 36;
#pragma unroll
            for (int k = 0; k < 9; k++) {
                unsigned long long wa, wb;
                lds_v2u64(wr + 4 * k, wa, wb);
                fma2(o2[2 * k], ff, wa);
                fma2(o2[2 * k + 1], ff, wb);
            }
        }
        float oc[36];
#pragma unroll
        for (int k = 0; k < 18; k++) unpack2(o2[k], oc[2 * k], oc[2 * k + 1]);
        float sd = 0.0f;
#pragma unroll
        for (int c = 0; c < 35; c++) sd += oc[c] * a2s[c];
        g_sdst[agg][base + tid] = sd;
        float* tr = tile + tid * 41;
#pragma unroll
        for (int c = 0; c < 35; c++) tr[c] = oc[c];
#pragma unroll
        for (int c = 35; c < 40; c++) tr[c] = 0.0f;   // pad halves 35..39
    }
    __syncthreads();

    // ---- coalesced fp16 store: 10 uint2 chunks per row, 128B row stride ----
    {
        __half* om = g_emb[agg];
        int idx = tid, r = tid / 10, k = tid - 10 * (tid / 10);
        for (; idx < cnt * 10; idx += 128) {
            const float* tr = tile + r * 41 + k * 4;
            __half2 h0 = __floats2half2_rn(tr[0], tr[1]);
            __half2 h1 = __floats2half2_rn(tr[2], tr[3]);
            uint2 u = make_uint2(*reinterpret_cast<unsigned int*>(&h0),
                                 *reinterpret_cast<unsigned int*>(&h1));
            *(uint2*)(om + (size_t)(base + r) * 64 + k * 4) = u;
            r += 12; k += 8; if (k >= 10) { k -= 10; r += 1; }
        }
    }
}

// ---------------------------------------------------------------------------
// Kernel 2: attention aggregation. One warp per (agg, node).
// 6 lane-groups of 5 process 6 edges/iteration; each active lane loads a
// 16B-aligned uint4 (8 halves) of its group's 128B-aligned row -> exactly
// 6 lines per LDG instruction. den reduction deferred past the gather loop.
// ---------------------------------------------------------------------------
__global__ void __launch_bounds__(256) aggregate_kernel(Params p) {
    __shared__ uint2 sh[8][36];           // {row offset in halves, w bits}
    const int wb   = threadIdx.x >> 5;
    const int lane = threadIdx.x & 31;
    const int gw   = blockIdx.x * 8 + wb;
    const int agg  = gw / N_NODES;
    const int node = gw - agg * N_NODES;

    int d = p.dst[agg][node * DEG + lane];
    float z  = g_ssrc[agg][node] + g_sdst[agg][d];   // compact s_dst array
    float u  = __expf(z);
    float el = (z > 0.0f) ? z : 0.1f * (u - 1.0f);   // elu(alpha=0.1)
    float w  = __expf(el);

    sh[wb][lane] = make_uint2((unsigned)d * 64u, __float_as_uint(w));
    if (lane < 4) sh[wb][32 + lane] = make_uint2(0u, 0u);   // pad: row 0, w=0
    __syncwarp();

    const int g = lane / 5;              // groups 0..5 active (30 lanes), 6 idle
    const int q = lane - 5 * g;
    float acc[8];
#pragma unroll
    for (int k = 0; k < 8; k++) acc[k] = 0.0f;

    if (g < 6) {
        const __half* tab = g_emb[agg];
#pragma unroll
        for (int t = 0; t < 6; t++) {
            uint2 ew = sh[wb][t * 6 + g];
            float we = __uint_as_float(ew.y);
            const uint4 v = *(const uint4*)(tab + ew.x + q * 8);
            const __half2* hp = (const __half2*)&v;
            float2 f0 = __half22float2(hp[0]);
            float2 f1 = __half22float2(hp[1]);
            float2 f2 = __half22float2(hp[2]);
            float2 f3 = __half22float2(hp[3]);
            acc[0] += we * f0.x; acc[1] += we * f0.y;
            acc[2] += we * f1.x; acc[3] += we * f1.y;
            acc[4] += we * f2.x; acc[5] += we * f2.y;
            acc[6] += we * f3.x; acc[7] += we * f3.y;
        }
    }

    // den reduction AFTER the gather: shuffle latency overlaps gather loads.
    float den = w;
#pragma unroll
    for (int o = 16; o; o >>= 1) den += __shfl_xor_sync(0xffffffffu, den, o);

    // fold 6 groups -> group 0 (lanes 0..4)
#pragma unroll
    for (int k = 0; k < 8; k++) {
        acc[k] += __shfl_down_sync(0xffffffffu, acc[k], 15);  // g<3 += g+3
        float b1 = __shfl_down_sync(0xffffffffu, acc[k], 5);
        float b2 = __shfl_down_sync(0xffffffffu, acc[k], 10);
        acc[k] += b1 + b2;
    }

    if (lane < 5) {
        float inv = 1.0f / den;
        float* om = g_m[agg] + (size_t)node * 40 + lane * 8;
        *(float4*)(om)     = make_float4(acc[0] * inv, acc[1] * inv, acc[2] * inv, acc[3] * inv);
        *(float4*)(om + 4) = make_float4(acc[4] * inv, acc[5] * inv, acc[6] * inv, acc[7] * inv);
    }
}

// ---------------------------------------------------------------------------
// Kernel 3: update MLP 105->70(PReLU)->35 (R5 structure, unchanged).
// ---------------------------------------------------------------------------
#define UPD_W1T   0
#define UPD_W2    (70 * 108)
#define UPD_B1    (UPD_W2 + 70 * 36)
#define UPD_B2    (UPD_B1 + 72)
#define UPD_TILE  (UPD_B2 + 40)
#define UPD_FLOATS (UPD_TILE + 128 * 37)
#define UPD_SMEM_BYTES (UPD_FLOATS * 4)

__global__ void __launch_bounds__(128) update_kernel(Params p) {
    extern __shared__ __align__(16) float usm[];
    float* W1T  = usm + UPD_W1T;
    float* W2s  = usm + UPD_W2;
    float* b1s  = usm + UPD_B1;
    float* b2s  = usm + UPD_B2;
    float* tile = usm + UPD_TILE;
    const int tid = threadIdx.x;

    for (int t = tid; t < 70 * 108; t += 128) {
        int j = t / 108, s = t - 108 * j;
        int os = (s < 35) ? s : (s == 35) ? -1 : (s < 71) ? s - 1 : (s == 71) ? -1 : (s < 107) ? s - 2 : -1;
        W1T[t] = (os >= 0) ? p.W1[os * 70 + j] : 0.0f;
    }
    for (int t = tid; t < 70 * 36; t += 128) {
        int j = t / 36, c = t - 36 * j;
        W2s[t] = (c < 35) ? p.W2[j * 35 + c] : 0.0f;
    }
    for (int t = tid; t < 70; t += 128) b1s[t] = p.b1[t];
    for (int t = tid; t < 36; t += 128) b2s[t] = (t < 35) ? p.b2[t] : 0.0f;
    float alpha_v = p.alpha[0];

    const int NBLK = (N_NODES + 127) / 128;
    const bool sideA = (blockIdx.x < NBLK);
    const int  bx   = sideA ? blockIdx.x : blockIdx.x - NBLK;
    const int  base = bx * 128;
    const int  cnt  = min(128, N_NODES - base);
    const float* fsrc = sideA ? p.fa : p.fb;
    const float* mpg  = (sideA ? g_m[0] : g_m[2]);
    const float* mng  = (sideA ? g_m[1] : g_m[3]);

    unsigned long long xp[54];

    __syncthreads();
    {
        int idx = tid, r = tid / 35, c = tid - 35 * (tid / 35);
        for (; idx < cnt * 35; idx += 128) {
            tile[r * 37 + c] = fsrc[base * 35 + idx];
            r += 3; c += 23; if (c >= 35) { c -= 35; r += 1; }
        }
    }
    __syncthreads();
    if (tid < cnt) {
        const float* xr = tile + tid * 37;
#pragma unroll
        for (int k = 0; k < 17; k++) xp[k] = pack2(xr[2 * k], xr[2 * k + 1]);
        xp[17] = pack2(xr[34], 0.0f);
    }
    __syncthreads();
    {
        int idx = tid, r = tid / 35, c = tid - 35 * (tid / 35);
        for (; idx < cnt * 35; idx += 128) {
            tile[r * 37 + c] = mpg[(size_t)(base + r) * 40 + c];
            r += 3; c += 23; if (c >= 35) { c -= 35; r += 1; }
        }
    }
    __syncthreads();
    if (tid < cnt) {
        const float* xr = tile + tid * 37;
#pragma unroll
        for (int k = 0; k < 17; k++) xp[18 + k] = pack2(xr[2 * k], xr[2 * k + 1]);
        xp[35] = pack2(xr[34], 0.0f);
    }
    __syncthreads();
    {
        int idx = tid, r = tid / 35, c = tid - 35 * (tid / 35);
        for (; idx < cnt * 35; idx += 128) {
            tile[r * 37 + c] = mng[(size_t)(base + r) * 40 + c];
            r += 3; c += 23; if (c >= 35) { c -= 35; r += 1; }
        }
    }
    __syncthreads();
    if (tid < cnt) {
        const float* xr = tile + tid * 37;
#pragma unroll
        for (int k = 0; k < 17; k++) xp[36 + k] = pack2(xr[2 * k], xr[2 * k + 1]);
        xp[53] = pack2(xr[34], 0.0f);
    }

    if (tid < cnt) {
        unsigned long long o2[18];
#pragma unroll
        for (int k = 0; k < 18; k++) o2[k] = pack2(b2s[2 * k], b2s[2 * k + 1]);

        for (int j = 0; j < 70; j++) {
            unsigned long long h2a = 0ull, h2b = 0ull;
            const float* wr = W1T + j * 108;
#pragma unroll
            for (int qq = 0; qq < 27; qq++) {
                unsigned long long wa, wb;
                lds_v2u64(wr + 4 * qq, wa, wb);
                fma2(h2a, xp[2 * qq], wa);
                fma2(h2b, xp[2 * qq + 1], wb);
            }
            float a0, a1, b0, b1v;
            unpack2(h2a, a0, a1); unpack2(h2b, b0, b1v);
            float hj = b1s[j] + ((a0 + a1) + (b0 + b1v));
            hj = (hj > 0.0f) ? hj : alpha_v * hj;
            unsigned long long hh = pack2(hj, hj);
            const float* w2r = W2s + j * 36;
#pragma unroll
            for (int k = 0; k < 9; k++) {
                unsigned long long wa, wb;
                lds_v2u64(w2r + 4 * k, wa, wb);
                fma2(o2[2 * k], hh, wa);
                fma2(o2[2 * k + 1], hh, wb);
            }
        }
        float* tr = tile + tid * 37;
#pragma unroll
        for (int k = 0; k < 18; k++) {
            float lo, hi; unpack2(o2[k], lo, hi);
            if (2 * k     < 35) tr[2 * k]     = lo;
            if (2 * k + 1 < 35) tr[2 * k + 1] = hi;
        }
    }
    __syncthreads();

    const int gbase = (sideA ? 0 : N_NODES) + base;
    {
        int idx = tid, r = tid / 35, c = tid - 35 * (tid / 35);
        for (; idx < cnt * 35; idx += 128) {
            p.out[gbase * 35 + idx] = tile[r * 37 + c];
            r += 3; c += 23; if (c >= 35) { c -= 35; r += 1; }
        }
    }
}

// ---------------------------------------------------------------------------
extern "C" void kernel_launch(void* const* d_in, const int* in_sizes, int n_in,
                              void* d_out, int out_size) {
    Params p;
    p.fa = (const float*)d_in[0];
    p.fb = (const float*)d_in[1];
    p.dst[0] = (const int*)d_in[2];
    p.dst[1] = (const int*)d_in[3];
    p.dst[2] = (const int*)d_in[4];
    p.dst[3] = (const int*)d_in[5];
    for (int k = 0; k < 4; k++) {
        p.W[k]   = (const float*)d_in[6 + 3 * k];
        p.bv[k]  = (const float*)d_in[7 + 3 * k];
        p.att[k] = (const float*)d_in[8 + 3 * k];
    }
    p.W1    = (const float*)d_in[18];
    p.b1    = (const float*)d_in[19];
    p.alpha = (const float*)d_in[20];
    p.W2    = (const float*)d_in[21];
    p.b2    = (const float*)d_in[22];
    p.out   = (float*)d_out;

    dim3 g1((N_NODES + 127) / 128, 4);
    transform_kernel<<<g1, 128>>>(p);

    aggregate_kernel<<<(4 * N_NODES) / 8, 256>>>(p);

    cudaFuncSetAttribute(update_kernel, cudaFuncAttributeMaxDynamicSharedMemorySize, UPD_SMEM_BYTES);
    update_kernel<<<2 * ((N_NODES + 127) / 128), 128, UPD_SMEM_BYTES>>>(p);
}

// round 13
// speedup vs baseline: 2.2969x; 1.2335x over previous
#include <cuda_runtime.h>
#include <cuda_fp16.h>
#include <math.h>

#define N_NODES 50000
#define EMB 35
#define DEG 32

// g_emb: fp16 transformed tables, 40-half rows (80B, 16B aligned, contiguous).
__device__ __align__(16) __half g_emb[4][N_NODES * 40];
__device__ float g_sdst[4][N_NODES];
__device__ float g_ssrc[4][N_NODES];
__device__ float g_m[4][N_NODES * 40];   // fp32 messages; cols >=35 garbage
// prepped update weights (built once per launch by prep_kernel)
__device__ __align__(16) float g_W1T[70 * 108];
__device__ __align__(16) float g_W2p[70 * 36];

struct Params {
    const float* fa; const float* fb;
    const int*   dst[4];
    const float* W[4]; const float* bv[4]; const float* att[4];
    const float* W1; const float* b1; const float* alpha; const float* W2; const float* b2;
    float* out;
};

// ---- packed f32x2 helpers (sm_103a FFMA2) ----------------------------------
__device__ __forceinline__ unsigned long long pack2(float lo, float hi) {
    unsigned long long r;
    asm("mov.b64 %0, {%1,%2};" : "=l"(r) : "f"(lo), "f"(hi));
    return r;
}
__device__ __forceinline__ void unpack2(unsigned long long v, float& lo, float& hi) {
    asm("mov.b64 {%0,%1}, %2;" : "=f"(lo), "=f"(hi) : "l"(v));
}
__device__ __forceinline__ void fma2(unsigned long long& d, unsigned long long a, unsigned long long b) {
    asm("fma.rn.f32x2 %0, %1, %2, %0;" : "+l"(d) : "l"(a), "l"(b));
}
__device__ __forceinline__ void lds_v2u64(const float* sp, unsigned long long& a, unsigned long long& b) {
    unsigned int addr = (unsigned int)__cvta_generic_to_shared(sp);
    asm("ld.shared.v2.u64 {%0,%1}, [%2];" : "=l"(a), "=l"(b) : "r"(addr));
}

// ---------------------------------------------------------------------------
// Kernel 0: one-block prep — build transposed/padded update weights in global.
// ---------------------------------------------------------------------------
__global__ void prep_kernel(Params p) {
    const int t0 = threadIdx.x;
    for (int i = t0; i < 70 * 108; i += 256) {
        int j = i / 108, s = i - 108 * j;
        int os = (s < 35) ? s : (s == 35) ? -1 : (s < 71) ? s - 1 : (s == 71) ? -1 : (s < 107) ? s - 2 : -1;
        g_W1T[i] = (os >= 0) ? p.W1[os * 70 + j] : 0.0f;
    }
    for (int i = t0; i < 70 * 36; i += 256) {
        int j = i / 36, c = i - 36 * j;
        g_W2p[i] = (c < 35) ? p.W2[j * 35 + c] : 0.0f;
    }
}

// ---------------------------------------------------------------------------
// Kernel 1: per-agg transform + attention scores. Block = 128 rows.
// All staging is pure linear float4/uint4 copies (block regions contiguous);
// tiles use stride 35 (odd -> conflict-free scalar reads).
// ---------------------------------------------------------------------------
__global__ void __launch_bounds__(128) transform_kernel(Params p) {
    const int agg = blockIdx.y;
    __shared__ __align__(16) float Ws[35 * 36];        // padded cols, col35 = 0
    __shared__ __align__(16) float tile[128 * 35];
    __shared__ __align__(16) uint2 utile[128 * 10];    // fp16-packed out rows
    __shared__ float bs[36], a1s[35], a2s[35];

    const int tid = threadIdx.x;
    {
        const float* W = p.W[agg];
        for (int t = tid; t < 35 * 36; t += 128) {
            int i = t / 36, c = t - 36 * i;
            Ws[t] = (c < 35) ? W[i * 35 + c] : 0.0f;
        }
        const float* bb = p.bv[agg];
        for (int t = tid; t < 36; t += 128) bs[t] = (t < 35) ? bb[t] : 0.0f;
        const float* at = p.att[agg];
        for (int t = tid; t < 35; t += 128) { a1s[t] = at[t]; a2s[t] = at[35 + t]; }
    }

    const int base = blockIdx.x * 128;
    const int cnt  = min(128, N_NODES - base);        // 128 or 80 (both *35 %4==0)
    const float* ftab = (agg < 2) ? p.fb : p.fa;
    const float* fsc  = (agg < 2) ? p.fa : p.fb;

    // ---- phase A: s_src (linear float4 stage, stride-35 tile) ----
    __syncthreads();
    {
        const float4* src = (const float4*)(fsc + (size_t)base * 35);
        const int n4 = (cnt * 35) >> 2;
        for (int i = tid; i < n4; i += 128) ((float4*)tile)[i] = src[i];
    }
    __syncthreads();
    if (tid < cnt) {
        float s1 = 0.0f;
        const float* xr = tile + tid * 35;
#pragma unroll
        for (int i = 0; i < 35; i++) s1 += xr[i] * a1s[i];
        g_ssrc[agg][base + tid] = s1;
    }
    __syncthreads();

    // ---- phase B: new_emb = ftab @ W + b, s_dst ----
    {
        const float4* src = (const float4*)(ftab + (size_t)base * 35);
        const int n4 = (cnt * 35) >> 2;
        for (int i = tid; i < n4; i += 128) ((float4*)tile)[i] = src[i];
    }
    __syncthreads();
    if (tid < cnt) {
        unsigned long long o2[18];
#pragma unroll
        for (int k = 0; k < 18; k++) o2[k] = pack2(bs[2 * k], bs[2 * k + 1]);
        const float* xr = tile + tid * 35;
#pragma unroll
        for (int i = 0; i < 35; i++) {
            float fi = xr[i];
            unsigned long long ff = pack2(fi, fi);
            const float* wr = Ws + i * 36;
#pragma unroll
            for (int k = 0; k < 9; k++) {
                unsigned long long wa, wb;
                lds_v2u64(wr + 4 * k, wa, wb);
                fma2(o2[2 * k], ff, wa);
                fma2(o2[2 * k + 1], ff, wb);
            }
        }
        float oc[36];
#pragma unroll
        for (int k = 0; k < 18; k++) unpack2(o2[k], oc[2 * k], oc[2 * k + 1]);
        float sd = 0.0f;
#pragma unroll
        for (int c = 0; c < 35; c++) sd += oc[c] * a2s[c];
        g_sdst[agg][base + tid] = sd;
        // pack own output row as fp16 uint2 chunks (halves 4k..4k+3)
        uint2* ur = utile + tid * 10;
#pragma unroll
        for (int k = 0; k < 9; k++) {        // covers halves 0..35 (oc[35]=0)
            __half2 h0 = __floats2half2_rn(oc[4 * k],     oc[4 * k + 1]);
            __half2 h1 = __floats2half2_rn(oc[4 * k + 2], oc[4 * k + 3]);
            ur[k] = make_uint2(*reinterpret_cast<unsigned*>(&h0),
                               *reinterpret_cast<unsigned*>(&h1));
        }
        ur[9] = make_uint2(0u, 0u);          // halves 36..39 = 0
    }
    __syncthreads();

    // ---- linear uint4 copy out (block's g_emb region is contiguous) ----
    {
        const uint4* su = (const uint4*)utile;
        uint4* du = (uint4*)(g_emb[agg] + (size_t)base * 40);
        const int n4 = cnt * 5;              // cnt rows * 10 uint2 / 2
        for (int i = tid; i < n4; i += 128) du[i] = su[i];
    }
}

// ---------------------------------------------------------------------------
// Kernel 2: attention aggregation — BIT-EXACT revert to the 302.9us version.
// One warp per (agg, node); 6 lane-groups of 5; 16B chunks of 80B fp16 rows.
// ---------------------------------------------------------------------------
__global__ void __launch_bounds__(256) aggregate_kernel(Params p) {
    __shared__ uint2 sh[8][36];           // {row offset in halves, w bits}
    const int wb   = threadIdx.x >> 5;
    const int lane = threadIdx.x & 31;
    const int gw   = blockIdx.x * 8 + wb;
    const int agg  = gw / N_NODES;
    const int node = gw - agg * N_NODES;

    int d = p.dst[agg][node * DEG + lane];
    float z  = g_ssrc[agg][node] + g_sdst[agg][d];
    float el = (z > 0.0f) ? z : 0.1f * expm1f(z);
    float w  = expf(el);

    float den = w;
#pragma unroll
    for (int o = 16; o; o >>= 1) den += __shfl_xor_sync(0xffffffffu, den, o);

    sh[wb][lane] = make_uint2((unsigned)d * 40u, __float_as_uint(w));
    if (lane < 4) sh[wb][32 + lane] = make_uint2(0u, 0u);   // pad: row 0, w=0
    __syncwarp();

    const int g = lane / 5;              // groups 0..5 active (30 lanes), 6 idle
    const int q = lane - 5 * g;
    float acc[8];
#pragma unroll
    for (int k = 0; k < 8; k++) acc[k] = 0.0f;

    if (g < 6) {
        const __half* tab = g_emb[agg];
#pragma unroll
        for (int t = 0; t < 6; t++) {
            uint2 ew = sh[wb][t * 6 + g];
            float we = __uint_as_float(ew.y);
            const uint4 v = *(const uint4*)(tab + ew.x + q * 8);
            const __half2* hp = (const __half2*)&v;
            float2 f0 = __half22float2(hp[0]);
            float2 f1 = __half22float2(hp[1]);
            float2 f2 = __half22float2(hp[2]);
            float2 f3 = __half22float2(hp[3]);
            acc[0] += we * f0.x; acc[1] += we * f0.y;
            acc[2] += we * f1.x; acc[3] += we * f1.y;
            acc[4] += we * f2.x; acc[5] += we * f2.y;
            acc[6] += we * f3.x; acc[7] += we * f3.y;
        }
    }

    // fold 6 groups -> group 0 (lanes 0..4)
#pragma unroll
    for (int k = 0; k < 8; k++) {
        acc[k] += __shfl_down_sync(0xffffffffu, acc[k], 15);  // g<3 += g+3
        float b1 = __shfl_down_sync(0xffffffffu, acc[k], 5);
        float b2 = __shfl_down_sync(0xffffffffu, acc[k], 10);
        acc[k] += b1 + b2;
    }

    if (lane < 5) {
        float inv = 1.0f / den;
        float* om = g_m[agg] + (size_t)node * 40 + lane * 8;
        *(float4*)(om)     = make_float4(acc[0] * inv, acc[1] * inv, acc[2] * inv, acc[3] * inv);
        *(float4*)(om + 4) = make_float4(acc[4] * inv, acc[5] * inv, acc[6] * inv, acc[7] * inv);
    }
}

// ---------------------------------------------------------------------------
// Kernel 3: update MLP 105->70(PReLU)->35. Weight smem filled by linear
// float4 copies from prepped globals; staging via linear/near-linear copies.
// ---------------------------------------------------------------------------
#define UPD_W1T   0
#define UPD_W2    (70 * 108)                 // 7560
#define UPD_B1    (UPD_W2 + 70 * 36)         // 10080
#define UPD_B2    (UPD_B1 + 72)              // 10152
#define UPD_TILE  (UPD_B2 + 40)              // 10192 (%4==0 -> 16B aligned)
#define UPD_FLOATS (UPD_TILE + 128 * 41)     // 15440
#define UPD_SMEM_BYTES (UPD_FLOATS * 4)

__global__ void __launch_bounds__(128) update_kernel(Params p) {
    extern __shared__ __align__(16) float usm[];
    float* W1T  = usm + UPD_W1T;
    float* W2s  = usm + UPD_W2;
    float* b1s  = usm + UPD_B1;
    float* b2s  = usm + UPD_B2;
    float* tile = usm + UPD_TILE;
    const int tid = threadIdx.x;

    // linear float4 copies of prepped weights
    for (int t = tid; t < (70 * 108) / 4; t += 128)
        ((float4*)W1T)[t] = ((const float4*)g_W1T)[t];
    for (int t = tid; t < (70 * 36) / 4; t += 128)
        ((float4*)W2s)[t] = ((const float4*)g_W2p)[t];
    for (int t = tid; t < 70; t += 128) b1s[t] = p.b1[t];
    for (int t = tid; t < 36; t += 128) b2s[t] = (t < 35) ? p.b2[t] : 0.0f;
    float alpha_v = p.alpha[0];

    const int NBLK = (N_NODES + 127) / 128;
    const bool sideA = (blockIdx.x < NBLK);
    const int  bx   = sideA ? blockIdx.x : blockIdx.x - NBLK;
    const int  base = bx * 128;
    const int  cnt  = min(128, N_NODES - base);
    const float* fsrc = sideA ? p.fa : p.fb;
    const float* mpg  = (sideA ? g_m[0] : g_m[2]);
    const float* mng  = (sideA ? g_m[1] : g_m[3]);

    unsigned long long xp[54];

    // segment 0: features — linear float4 stage, stride-35 tile
    __syncthreads();
    {
        const float4* src = (const float4*)(fsrc + (size_t)base * 35);
        const int n4 = (cnt * 35) >> 2;
        for (int i = tid; i < n4; i += 128) ((float4*)tile)[i] = src[i];
    }
    __syncthreads();
    if (tid < cnt) {
        const float* xr = tile + tid * 35;
#pragma unroll
        for (int k = 0; k < 17; k++) xp[k] = pack2(xr[2 * k], xr[2 * k + 1]);
        xp[17] = pack2(xr[34], 0.0f);
    }
    __syncthreads();
    // segment 1: m_pos — float4 loads, scalar STS into stride-41 tile
    {
        const float4* src = (const float4*)(mpg + (size_t)base * 40);
        int i = tid, r = tid / 10, c = tid - 10 * (tid / 10);
        for (; i < cnt * 10; i += 128) {
            float4 v = src[i];
            float* dst = tile + r * 41 + c * 4;
            dst[0] = v.x; dst[1] = v.y; dst[2] = v.z; dst[3] = v.w;
            r += 12; c += 8; if (c >= 10) { c -= 10; r += 1; }
        }
    }
    __syncthreads();
    if (tid < cnt) {
        const float* xr = tile + tid * 41;
#pragma unroll
        for (int k = 0; k < 17; k++) xp[18 + k] = pack2(xr[2 * k], xr[2 * k + 1]);
        xp[35] = pack2(xr[34], 0.0f);
    }
    __syncthreads();
    // segment 2: m_neg
    {
        const float4* src = (const float4*)(mng + (size_t)base * 40);
        int i = tid, r = tid / 10, c = tid - 10 * (tid / 10);
        for (; i < cnt * 10; i += 128) {
            float4 v = src[i];
            float* dst = tile + r * 41 + c * 4;
            dst[0] = v.x; dst[1] = v.y; dst[2] = v.z; dst[3] = v.w;
            r += 12; c += 8; if (c >= 10) { c -= 10; r += 1; }
        }
    }
    __syncthreads();
    if (tid < cnt) {
        const float* xr = tile + tid * 41;
#pragma unroll
        for (int k = 0; k < 17; k++) xp[36 + k] = pack2(xr[2 * k], xr[2 * k + 1]);
        xp[53] = pack2(xr[34], 0.0f);
    }
    __syncthreads();

    if (tid < cnt) {
        unsigned long long o2[18];
#pragma unroll
        for (int k = 0; k < 18; k++) o2[k] = pack2(b2s[2 * k], b2s[2 * k + 1]);

        for (int j = 0; j < 70; j++) {
            unsigned long long h2a = 0ull, h2b = 0ull;
            const float* wr = W1T + j * 108;
#pragma unroll
            for (int qq = 0; qq < 27; qq++) {
                unsigned long long wa, wb;
                lds_v2u64(wr + 4 * qq, wa, wb);
                fma2(h2a, xp[2 * qq], wa);
                fma2(h2b, xp[2 * qq + 1], wb);
            }
            float a0, a1, b0, b1v;
            unpack2(h2a, a0, a1); unpack2(h2b, b0, b1v);
            float hj = b1s[j] + ((a0 + a1) + (b0 + b1v));
            hj = (hj > 0.0f) ? hj : alpha_v * hj;
            unsigned long long hh = pack2(hj, hj);
            const float* w2r = W2s + j * 36;
#pragma unroll
            for (int k = 0; k < 9; k++) {
                unsigned long long wa, wb;
                lds_v2u64(w2r + 4 * k, wa, wb);
                fma2(o2[2 * k], hh, wa);
                fma2(o2[2 * k + 1], hh, wb);
            }
        }
        // stage output row (stride-35 tile, conflict-free scalar writes)
        float* tr = tile + tid * 35;
#pragma unroll
        for (int k = 0; k < 18; k++) {
            float lo, hi; unpack2(o2[k], lo, hi);
            if (2 * k     < 35) tr[2 * k]     = lo;
            if (2 * k + 1 < 35) tr[2 * k + 1] = hi;
        }
    }
    __syncthreads();

    // linear float4 copy to output
    {
        const int gbase = (sideA ? 0 : N_NODES) + base;
        float4* dst = (float4*)(p.out + (size_t)gbase * 35);
        const int n4 = (cnt * 35) >> 2;
        for (int i = tid; i < n4; i += 128) dst[i] = ((const float4*)tile)[i];
    }
}

// ---------------------------------------------------------------------------
extern "C" void kernel_launch(void* const* d_in, const int* in_sizes, int n_in,
                              void* d_out, int out_size) {
    Params p;
    p.fa = (const float*)d_in[0];
    p.fb = (const float*)d_in[1];
    p.dst[0] = (const int*)d_in[2];
    p.dst[1] = (const int*)d_in[3];
    p.dst[2] = (const int*)d_in[4];
    p.dst[3] = (const int*)d_in[5];
    for (int k = 0; k < 4; k++) {
        p.W[k]   = (const float*)d_in[6 + 3 * k];
        p.bv[k]  = (const float*)d_in[7 + 3 * k];
        p.att[k] = (const float*)d_in[8 + 3 * k];
    }
    p.W1    = (const float*)d_in[18];
    p.b1    = (const float*)d_in[19];
    p.alpha = (const float*)d_in[20];
    p.W2    = (const float*)d_in[21];
    p.b2    = (const float*)d_in[22];
    p.out   = (float*)d_out;

    prep_kernel<<<1, 256>>>(p);

    dim3 g1((N_NODES + 127) / 128, 4);
    transform_kernel<<<g1, 128>>>(p);

    aggregate_kernel<<<(4 * N_NODES) / 8, 256>>>(p);

    cudaFuncSetAttribute(update_kernel, cudaFuncAttributeMaxDynamicSharedMemorySize, UPD_SMEM_BYTES);
    update_kernel<<<2 * ((N_NODES + 127) / 128), 128, UPD_SMEM_BYTES>>>(p);
}